// round 1
// baseline (speedup 1.0000x reference)
#include <cuda_runtime.h>
#include <cuda_bf16.h>
#include <math.h>

// Problem constants (fixed shapes for this dataset)
#define NIMG 16
#define CCH  32
#define HF   256
#define WF   256
#define HEIGHT_R 8
#define MAXW 128
#define MBOX 1024

// Scratch (allocation-free rule: __device__ globals)
__device__ float g_p1x[MBOX], g_p1y[MBOX];
__device__ float g_axx[MBOX], g_axy[MBOX];
__device__ float g_ayx[MBOX], g_ayy[MBOX];
__device__ int   g_width[MBOX];
__device__ int   g_order[MBOX];

// ---------------------------------------------------------------------------
// Kernel 1: per-box geometry + width.  Width must match the reference bit-for-
// bit in its discrete outcome, so use explicit round-to-nearest intrinsics and
// avoid FMA contraction in the norm/ratio computation.
// ---------------------------------------------------------------------------
__global__ void prep_kernel(const float* __restrict__ boxes, int M) {
    int i = blockIdx.x * blockDim.x + threadIdx.x;
    if (i >= M) return;
    const float* b = boxes + i * 8;
    // p = boxes / 4  (multiply by 0.25 is exact)
    float p1x = b[0] * 0.25f, p1y = b[1] * 0.25f;
    float p2x = b[2] * 0.25f, p2y = b[3] * 0.25f;
    float p4x = b[6] * 0.25f, p4y = b[7] * 0.25f;

    float dx2 = __fadd_rn(p2x, -p1x), dy2 = __fadd_rn(p2y, -p1y);
    float dx4 = __fadd_rn(p4x, -p1x), dy4 = __fadd_rn(p4y, -p1y);

    float bw = __fsqrt_rn(__fadd_rn(__fmul_rn(dx2, dx2), __fmul_rn(dy2, dy2)));
    float bh = __fsqrt_rn(__fadd_rn(__fmul_rn(dx4, dx4), __fmul_rn(dy4, dy4)));

    float bmaj = bw, bmin = bh;
    if (bw <= bh) { bmaj = bh; bmin = bw; }   // swap

    // width = clip(ceil(8*bmaj / max(bmin,1e-6)), 1, 128)
    float num   = __fmul_rn(8.0f, bmaj);      // *8 exact anyway
    float den   = fmaxf(bmin, 1e-6f);
    float ratio = __fdiv_rn(num, den);
    float wcl   = fminf(fmaxf(ceilf(ratio), 1.0f), 128.0f);
    int   w     = (int)wcl;

    // ax = (p2-p1)/width ;  ay = (p4-p1)/8  (/8 exact)
    float wf = (float)w;
    g_axx[i] = __fdiv_rn(dx2, wf);
    g_axy[i] = __fdiv_rn(dy2, wf);
    g_ayx[i] = dx4 * 0.125f;
    g_ayy[i] = dy4 * 0.125f;
    g_p1x[i] = p1x; g_p1y[i] = p1y;
    g_width[i] = w;
}

// ---------------------------------------------------------------------------
// Kernel 2: stable descending argsort of width via O(M^2) rank counting in one
// block.  rank[i] = #{j : w[j] > w[i]} + #{j < i : w[j] == w[i]}  (stable).
// Optionally writes the width[order] / order tail of the output as floats.
// ---------------------------------------------------------------------------
__global__ void sort_kernel(float* __restrict__ out_tail, int M, int write_tail) {
    __shared__ int sw[MBOX];
    int i = threadIdx.x;
    int w = (i < M) ? g_width[i] : -1;
    if (i < MBOX) sw[i] = w;
    __syncthreads();
    if (i < M) {
        int rank = 0;
        #pragma unroll 8
        for (int j = 0; j < MBOX; j++) {
            int wj = sw[j];
            rank += (wj > w) | ((wj == w) & (j < i));
        }
        g_order[rank] = i;
        if (write_tail) {
            out_tail[rank]     = (float)w;   // width[order]
            out_tail[M + rank] = (float)i;   // order
        }
    }
}

// ---------------------------------------------------------------------------
// Kernel 3: main sampler.  One block per (sorted slot k, output row y).
// 256 threads = 8 warps.  lane = x (spatially local gather), warps 0-3 cover
// x 0..127 for channels 0..15, warps 4-7 for channels 16..31.  Results staged
// in padded SMEM [128][33] then written c-innermost with float4 stores.
// ---------------------------------------------------------------------------
__global__ __launch_bounds__(256) void sample_kernel(
    const float* __restrict__ fm,
    const int*   __restrict__ mapping,
    float*       __restrict__ out)
{
    const int b = blockIdx.x;
    const int k = b >> 3;       // sorted slot
    const int y = b & 7;        // output row
    const int box = g_order[k];
    const int width = g_width[box];
    const int n = mapping[box];

    __shared__ float s[MAXW * 33];

    const int tid  = threadIdx.x;
    const int lane = tid & 31;
    const int wrp  = tid >> 5;
    const int x    = ((wrp & 3) << 5) | lane;   // 0..127
    const int c0   = (wrp >> 2) << 4;           // 0 or 16

    float* srow = s + x * 33 + c0;

    if (x < width) {
        const float fx = (float)x, fy = (float)y;
        const float sx = g_p1x[box] + g_axx[box] * fx + g_ayx[box] * fy;
        const float sy = g_p1y[box] + g_axy[box] * fx + g_ayy[box] * fy;
        const float x0f = floorf(sx), y0f = floorf(sy);
        const float tx = sx - x0f, ty = sy - y0f;
        const int x0 = (int)x0f, y0 = (int)y0f;
        const int x1 = x0 + 1,  y1 = y0 + 1;

        const bool vx0 = (x0 >= 0) & (x0 < WF);
        const bool vx1 = (x1 >= 0) & (x1 < WF);
        const bool vy0 = (y0 >= 0) & (y0 < HF);
        const bool vy1 = (y1 >= 0) & (y1 < HF);

        // fold validity into the bilinear weights
        float w00 = (1.f - tx) * (1.f - ty); if (!(vx0 & vy0)) w00 = 0.f;
        float w01 = tx * (1.f - ty);         if (!(vx1 & vy0)) w01 = 0.f;
        float w10 = (1.f - tx) * ty;         if (!(vx0 & vy1)) w10 = 0.f;
        float w11 = tx * ty;                 if (!(vx1 & vy1)) w11 = 0.f;

        const int xc0 = min(max(x0, 0), WF - 1);
        const int xc1 = min(max(x1, 0), WF - 1);
        const int yc0 = min(max(y0, 0), HF - 1);
        const int yc1 = min(max(y1, 0), HF - 1);

        const long o00 = yc0 * WF + xc0;
        const long o01 = yc0 * WF + xc1;
        const long o10 = yc1 * WF + xc0;
        const long o11 = yc1 * WF + xc1;

        const float* base = fm + ((size_t)n * CCH + c0) * (size_t)(HF * WF);

        #pragma unroll
        for (int cc = 0; cc < 16; cc++) {
            const float* p = base + (size_t)cc * (HF * WF);
            float r = w00 * __ldg(p + o00) + w01 * __ldg(p + o01)
                    + w10 * __ldg(p + o10) + w11 * __ldg(p + o11);
            srow[cc] = r;
        }
    } else {
        #pragma unroll
        for (int cc = 0; cc < 16; cc++) srow[cc] = 0.f;
    }
    __syncthreads();

    // coalesced writeout: element index e = x*32 + c  (c innermost)
    float4* orow = (float4*)(out + ((size_t)k * HEIGHT_R + y) * (MAXW * CCH));
    #pragma unroll
    for (int j = 0; j < 4; j++) {
        int v = tid + j * 256;      // float4 index 0..1023
        int e = v << 2;             // element index
        int xx = e >> 5;
        int cc = e & 31;
        const float* sp = s + xx * 33 + cc;
        float4 val;
        val.x = sp[0]; val.y = sp[1]; val.z = sp[2]; val.w = sp[3];
        orow[v] = val;
    }
}

// ---------------------------------------------------------------------------
extern "C" void kernel_launch(void* const* d_in, const int* in_sizes, int n_in,
                              void* d_out, int out_size) {
    const float* fm      = (const float*)d_in[0];
    const float* boxes   = (const float*)d_in[1];
    const int*   mapping = (const int*)  d_in[2];
    float*       out     = (float*)d_out;

    const int M = in_sizes[1] / 8;                       // 1024
    const size_t main_elems = (size_t)M * HEIGHT_R * MAXW * CCH;
    const int write_tail = ((size_t)out_size >= main_elems + 2 * (size_t)M) ? 1 : 0;

    prep_kernel<<<(M + 255) / 256, 256>>>(boxes, M);
    sort_kernel<<<1, MBOX>>>(out + main_elems, M, write_tail);
    sample_kernel<<<M * HEIGHT_R, 256>>>(fm, mapping, out);
}